// round 1
// baseline (speedup 1.0000x reference)
#include <cuda_runtime.h>
#include <cstdint>

#define TT 160
#define BB 256
#define CIN 512
#define HH 256
#define GG 1024
#define NBAR 321
#define RNCTA 128

// ---------------- static scratch (no allocs allowed) ----------------
__device__ float d_XG[(size_t)TT * 2 * BB * GG];   // [T][2][B][G] input-gate preactivations (+bias)
__device__ float d_H0[(size_t)TT * BB * (2 * HH)]; // layer-0 output [T][B][512]
__device__ float d_Gtmp[2 * BB * GG];              // per-step gates
__device__ float d_Hst[2 * BB * HH];               // h state per dir
__device__ unsigned d_flags[NBAR];                 // grid barrier flags (zero-init)

// ---------------- helpers ----------------
__device__ __forceinline__ unsigned f2tf(float x) {
    unsigned u;
    asm("cvt.rna.tf32.f32 %0, %1;" : "=r"(u) : "f"(x));
    return u;
}
__device__ __forceinline__ float tf32r(float x) { return __uint_as_float(f2tf(x)); }

__device__ __forceinline__ void mma_tf32(float* c, const unsigned* a, const unsigned* b) {
    asm volatile(
        "mma.sync.aligned.m16n8k8.row.col.f32.tf32.tf32.f32 "
        "{%0,%1,%2,%3}, {%4,%5,%6,%7}, {%8,%9}, {%0,%1,%2,%3};"
        : "+f"(c[0]), "+f"(c[1]), "+f"(c[2]), "+f"(c[3])
        : "r"(a[0]), "r"(a[1]), "r"(a[2]), "r"(a[3]), "r"(b[0]), "r"(b[1]));
}

__device__ __forceinline__ void cp16(float* dst, const float* src) {
    unsigned d = (unsigned)__cvta_generic_to_shared(dst);
    asm volatile("cp.async.cg.shared.global [%0], [%1], 16;" ::"r"(d), "l"(src));
}

__device__ __forceinline__ float sigf(float x) { return 1.f / (1.f + __expf(-x)); }

// Grid-wide barrier, phase-indexed flags, lazily reset (replay-safe).
__device__ __forceinline__ void gridbar(int k) {
    __syncthreads();
    if (threadIdx.x == 0) {
        __threadfence();
        atomicAdd(&d_flags[k], 1u);
        while (*(volatile unsigned*)&d_flags[k] < (unsigned)RNCTA) __nanosleep(32);
        if (blockIdx.x == 0 && k > 0) *(volatile unsigned*)&d_flags[k - 1] = 0;
    }
    __syncthreads();
    __threadfence();
}

// ---------------- input GEMM: XG[t][dir][b][g] = A @ Wih^T + (bih+bhh) ----------------
// M=40960, N=1024 (per dir), K=512. CTA tile 128x128, BK=16, tf32 mma, cp.async 2-stage.
#define BM 128
#define BN 128
#define BK 16
#define SAST 20 // 16 + 4 pad -> conflict-free fragment LDS

__global__ void __launch_bounds__(256) igemm_kernel(
    const float* __restrict__ Ax, int useH0,
    const float* __restrict__ Wf, const float* __restrict__ Wb,
    const float* __restrict__ bif, const float* __restrict__ bhf,
    const float* __restrict__ bib, const float* __restrict__ bhb) {
    __shared__ float sA[2][BM][SAST];
    __shared__ float sB[2][BN][SAST];

    const float* A = useH0 ? (const float*)d_H0 : Ax;
    const int dir = blockIdx.z;
    const float* W = dir ? Wb : Wf;
    const float* bi = dir ? bib : bif;
    const float* bh = dir ? bhb : bhf;
    const int m0 = blockIdx.y * BM;
    const int n0 = blockIdx.x * BN;
    const int tid = threadIdx.x;
    const int w = tid >> 5, lane = tid & 31;
    const int wm = w >> 2, wn = w & 3; // 2 x 4 warps, warp tile 64(M) x 32(N)
    const int g_ = lane >> 2, tg = lane & 3;

    float acc[4][4][4];
#pragma unroll
    for (int i = 0; i < 4; i++)
#pragma unroll
        for (int j = 0; j < 4; j++)
#pragma unroll
            for (int q = 0; q < 4; q++) acc[i][j][q] = 0.f;

    auto load_stage = [&](int s, int k0) {
#pragma unroll
        for (int i = 0; i < 2; i++) {
            int c = tid + i * 256; // 512 16B-chunks per tile
            int row = c >> 2, cc = c & 3;
            cp16(&sA[s][row][cc * 4], A + (size_t)(m0 + row) * CIN + k0 + cc * 4);
            cp16(&sB[s][row][cc * 4], W + (size_t)(n0 + row) * CIN + k0 + cc * 4);
        }
        asm volatile("cp.async.commit_group;");
    };

    load_stage(0, 0);
    const int KT = CIN / BK; // 32
    for (int kt = 0; kt < KT; kt++) {
        if (kt < KT - 1) {
            load_stage((kt + 1) & 1, (kt + 1) * BK);
            asm volatile("cp.async.wait_group 1;");
        } else {
            asm volatile("cp.async.wait_group 0;");
        }
        __syncthreads();
        const int s = kt & 1;
#pragma unroll
        for (int kk = 0; kk < BK; kk += 8) {
            unsigned a[4][4], b[4][2];
#pragma unroll
            for (int mt = 0; mt < 4; mt++) {
                int r = wm * 64 + mt * 16 + g_;
                a[mt][0] = f2tf(sA[s][r][kk + tg]);
                a[mt][1] = f2tf(sA[s][r + 8][kk + tg]);
                a[mt][2] = f2tf(sA[s][r][kk + tg + 4]);
                a[mt][3] = f2tf(sA[s][r + 8][kk + tg + 4]);
            }
#pragma unroll
            for (int nt = 0; nt < 4; nt++) {
                int n = wn * 32 + nt * 8 + g_;
                b[nt][0] = f2tf(sB[s][n][kk + tg]);
                b[nt][1] = f2tf(sB[s][n][kk + tg + 4]);
            }
#pragma unroll
            for (int mt = 0; mt < 4; mt++)
#pragma unroll
                for (int nt = 0; nt < 4; nt++) mma_tf32(acc[mt][nt], a[mt], b[nt]);
        }
        __syncthreads();
    }

    // epilogue: add (bih+bhh), write XG[t][dir][b][g]
#pragma unroll
    for (int mt = 0; mt < 4; mt++) {
#pragma unroll
        for (int nt = 0; nt < 4; nt++) {
            int col = n0 + wn * 32 + nt * 8 + tg * 2;
            float b0v = bi[col] + bh[col];
            float b1v = bi[col + 1] + bh[col + 1];
#pragma unroll
            for (int hh = 0; hh < 2; hh++) {
                int row = m0 + wm * 64 + mt * 16 + g_ + hh * 8;
                int tt = row >> 8, bb = row & 255;
                float2 v;
                v.x = acc[mt][nt][hh * 2 + 0] + b0v;
                v.y = acc[mt][nt][hh * 2 + 1] + b1v;
                *(float2*)&d_XG[(((size_t)tt * 2 + dir) * BB + bb) * GG + col] = v;
            }
        }
    }
}

// ---------------- persistent recurrence kernel ----------------
// 128 CTAs: dir = cta>>6; 64 CTAs/dir tile [256 B x 1024 G] as 4(B) x 16(G) tiles of 64x64.
// Whh slice cached in smem for the whole layer; 2 grid barriers per step.
#define SMEMREC (2 * 64 * 260 * 4)

__global__ void __launch_bounds__(256) recur_kernel(
    const float* __restrict__ Whf, const float* __restrict__ Whb,
    float* __restrict__ outp, int writeOut) {
    extern __shared__ float sm[];
    float* ws = sm;            // [64][260] Whh slice (tf32-rounded)
    float* hs = sm + 64 * 260; // [64][260] h tile

    const int cta = blockIdx.x;
    const int tid = threadIdx.x;
    const int dir = cta >> 6;
    const int sub = cta & 63;
    const int b0 = (sub >> 4) * 64;
    const int g0 = (sub & 15) * 64;
    const float* Wh = dir ? Whb : Whf;
    float* outb = writeOut ? outp : (float*)d_H0;

    const int w = tid >> 5, lane = tid & 31;
    const int wm = w >> 2, wn = w & 3; // 2 x 4 warps, warp tile 32(M) x 16(N)
    const int g_ = lane >> 2, tg = lane & 3;

    // reset the one leftover flag from the previous launch (safe: flags[NBAR-1] is
    // only reachable after this CTA-0 store is ordered by earlier barriers)
    if (cta == 0 && tid == 0) *(volatile unsigned*)&d_flags[NBAR - 1] = 0;

    // cache Whh slice rows [g0, g0+64) x 256 (tf32-rounded)
    for (int i = tid; i < 64 * 64; i += 256) {
        int r = i >> 6, c4 = i & 63;
        float4 v = *(const float4*)&Wh[(size_t)(g0 + r) * HH + c4 * 4];
        v.x = tf32r(v.x); v.y = tf32r(v.y); v.z = tf32r(v.z); v.w = tf32r(v.w);
        *(float4*)&ws[r * 260 + c4 * 4] = v;
    }

    // pointwise mapping: 1 float4 of h per thread, c-state kept in registers
    const int gtid = cta * 256 + tid;           // [0, 32768)
    const int pdir = gtid >> 14;
    const int pb = (gtid >> 6) & 255;
    const int pj = (gtid & 63) * 4;
    float4 cst = make_float4(0.f, 0.f, 0.f, 0.f);
    *(float4*)&d_Hst[(pdir * BB + pb) * HH + pj] = cst; // h0 = 0

    gridbar(0);
    int kbar = 1;

    for (int s = 0; s < TT; s++) {
        const int t = dir ? (TT - 1 - s) : s;

        // phase 1: load h tile, GEMM, gates += XG, write Gtmp
        for (int i = tid; i < 64 * 64; i += 256) {
            int r = i >> 6, c4 = i & 63;
            float4 v = __ldcg((const float4*)&d_Hst[(dir * BB + b0 + r) * HH + c4 * 4]);
            v.x = tf32r(v.x); v.y = tf32r(v.y); v.z = tf32r(v.z); v.w = tf32r(v.w);
            *(float4*)&hs[r * 260 + c4 * 4] = v;
        }
        __syncthreads();

        float acc[2][2][4];
#pragma unroll
        for (int i = 0; i < 2; i++)
#pragma unroll
            for (int j = 0; j < 2; j++)
#pragma unroll
                for (int q = 0; q < 4; q++) acc[i][j][q] = 0.f;

        const unsigned* hsU = (const unsigned*)hs;
        const unsigned* wsU = (const unsigned*)ws;
#pragma unroll 4
        for (int k8 = 0; k8 < 32; k8++) {
            const int kk = k8 * 8;
            unsigned a[2][4], b[2][2];
#pragma unroll
            for (int mt = 0; mt < 2; mt++) {
                int r = wm * 32 + mt * 16 + g_;
                a[mt][0] = hsU[r * 260 + kk + tg];
                a[mt][1] = hsU[(r + 8) * 260 + kk + tg];
                a[mt][2] = hsU[r * 260 + kk + tg + 4];
                a[mt][3] = hsU[(r + 8) * 260 + kk + tg + 4];
            }
#pragma unroll
            for (int nt = 0; nt < 2; nt++) {
                int n = wn * 16 + nt * 8 + g_;
                b[nt][0] = wsU[n * 260 + kk + tg];
                b[nt][1] = wsU[n * 260 + kk + tg + 4];
            }
#pragma unroll
            for (int mt = 0; mt < 2; mt++)
#pragma unroll
                for (int nt = 0; nt < 2; nt++) mma_tf32(acc[mt][nt], a[mt], b[nt]);
        }

        const size_t tb = ((size_t)t * 2 + dir) * BB;
#pragma unroll
        for (int mt = 0; mt < 2; mt++) {
#pragma unroll
            for (int nt = 0; nt < 2; nt++) {
                int col = g0 + wn * 16 + nt * 8 + tg * 2;
#pragma unroll
                for (int hh = 0; hh < 2; hh++) {
                    int row = b0 + wm * 32 + mt * 16 + g_ + hh * 8;
                    float2 xg = __ldcg((const float2*)&d_XG[(tb + row) * GG + col]);
                    float2 v;
                    v.x = acc[mt][nt][hh * 2 + 0] + xg.x;
                    v.y = acc[mt][nt][hh * 2 + 1] + xg.y;
                    *(float2*)&d_Gtmp[(dir * BB + row) * GG + col] = v;
                }
            }
        }
        gridbar(kbar++);

        // phase 2: pointwise LSTM cell (c in registers), write h to state + output
        {
            const int t2 = pdir ? (TT - 1 - s) : s;
            const float* gp = &d_Gtmp[(pdir * BB + pb) * GG + pj];
            float4 gi = __ldcg((const float4*)(gp));
            float4 gf = __ldcg((const float4*)(gp + 256));
            float4 gc = __ldcg((const float4*)(gp + 512));
            float4 go = __ldcg((const float4*)(gp + 768));
            cst.x = sigf(gf.x) * cst.x + sigf(gi.x) * tanhf(gc.x);
            cst.y = sigf(gf.y) * cst.y + sigf(gi.y) * tanhf(gc.y);
            cst.z = sigf(gf.z) * cst.z + sigf(gi.z) * tanhf(gc.z);
            cst.w = sigf(gf.w) * cst.w + sigf(gi.w) * tanhf(gc.w);
            float4 hv;
            hv.x = sigf(go.x) * tanhf(cst.x);
            hv.y = sigf(go.y) * tanhf(cst.y);
            hv.z = sigf(go.z) * tanhf(cst.z);
            hv.w = sigf(go.w) * tanhf(cst.w);
            *(float4*)&d_Hst[(pdir * BB + pb) * HH + pj] = hv;
            *(float4*)&outb[((size_t)t2 * BB + pb) * (2 * HH) + pdir * HH + pj] = hv;
        }
        gridbar(kbar++);
    }
}

// ---------------- launch ----------------
extern "C" void kernel_launch(void* const* d_in, const int* in_sizes, int n_in,
                              void* d_out, int out_size) {
    (void)in_sizes; (void)n_in; (void)out_size;
    const float* x = (const float*)d_in[0];
    const float* wih0f = (const float*)d_in[1];
    const float* whh0f = (const float*)d_in[2];
    const float* bih0f = (const float*)d_in[3];
    const float* bhh0f = (const float*)d_in[4];
    const float* wih0b = (const float*)d_in[5];
    const float* whh0b = (const float*)d_in[6];
    const float* bih0b = (const float*)d_in[7];
    const float* bhh0b = (const float*)d_in[8];
    const float* wih1f = (const float*)d_in[9];
    const float* whh1f = (const float*)d_in[10];
    const float* bih1f = (const float*)d_in[11];
    const float* bhh1f = (const float*)d_in[12];
    const float* wih1b = (const float*)d_in[13];
    const float* whh1b = (const float*)d_in[14];
    const float* bih1b = (const float*)d_in[15];
    const float* bhh1b = (const float*)d_in[16];
    float* out = (float*)d_out;

    cudaFuncSetAttribute(recur_kernel, cudaFuncAttributeMaxDynamicSharedMemorySize, SMEMREC);

    dim3 gg(GG / BN, (TT * BB) / BM, 2); // (8, 320, 2)

    // layer 0
    igemm_kernel<<<gg, 256>>>(x, 0, wih0f, wih0b, bih0f, bhh0f, bih0b, bhh0b);
    recur_kernel<<<RNCTA, 256, SMEMREC>>>(whh0f, whh0b, nullptr, 0);
    // layer 1
    igemm_kernel<<<gg, 256>>>(nullptr, 1, wih1f, wih1b, bih1f, bhh1f, bih1b, bhh1b);
    recur_kernel<<<RNCTA, 256, SMEMREC>>>(whh1f, whh1b, out, 1);
}

// round 2
// speedup vs baseline: 1.5640x; 1.5640x over previous
#include <cuda_runtime.h>
#include <cstdint>

#define TT 160
#define BB 256
#define CIN 512
#define HH 256
#define GG 1024
#define RNCTA 128
#define WPITCH 264   // smem row pitch (floats) for ws/hs; 264 mod 32 == 8 -> conflict-free paired LDS.64
#define SGPITCH 68   // gate-exchange pitch; 68*4 = 272 = 16*17 -> float4-aligned rows

// ---------------- static scratch (no allocs allowed) ----------------
__device__ float d_XG[(size_t)TT * 2 * BB * GG];   // [T][2][B][G] input preactivations (+bias)
__device__ float d_H0[(size_t)TT * BB * (2 * HH)]; // layer-0 output [T][B][512]
__device__ float d_HstS[2 * BB * HH];              // h state, tf32-rounded, pair-swizzled cols
__device__ __align__(128) unsigned d_gflags[8 * 32]; // per-group monotonic counters

// ---------------- helpers ----------------
__device__ __forceinline__ unsigned f2tf(float x) {
    unsigned u;
    asm("cvt.rna.tf32.f32 %0, %1;" : "=r"(u) : "f"(x));
    return u;
}
__device__ __forceinline__ float tf32r(float x) { return __uint_as_float(f2tf(x)); }

__device__ __forceinline__ void mma_tf32(float* c, const unsigned* a, const unsigned* b) {
    asm volatile(
        "mma.sync.aligned.m16n8k8.row.col.f32.tf32.tf32.f32 "
        "{%0,%1,%2,%3}, {%4,%5,%6,%7}, {%8,%9}, {%0,%1,%2,%3};"
        : "+f"(c[0]), "+f"(c[1]), "+f"(c[2]), "+f"(c[3])
        : "r"(a[0]), "r"(a[1]), "r"(a[2]), "r"(a[3]), "r"(b[0]), "r"(b[1]));
}

__device__ __forceinline__ void cp16(float* dst, const float* src) {
    unsigned d = (unsigned)__cvta_generic_to_shared(dst);
    asm volatile("cp.async.cg.shared.global [%0], [%1], 16;" ::"r"(d), "l"(src));
}

__device__ __forceinline__ float sigf(float x) { return 1.f / (1.f + __expf(-x)); }

// pair-swizzle position: k -> (k&~7) + (k&3)*2 + ((k>>2)&1)  (so k and k+4 are adjacent)
__device__ __forceinline__ int pswz(int k) {
    return (k & ~7) + ((k & 3) << 1) + ((k >> 2) & 1);
}

// group barrier: thread 0 fences + arrives + polls a monotonic counter
__device__ __forceinline__ void gbar(unsigned* flag, unsigned target) {
    __syncthreads();
    if (threadIdx.x == 0) {
        __threadfence();
        atomicAdd(flag, 1u);
        while (*(volatile unsigned*)flag < target) {}
        __threadfence();
    }
    __syncthreads();
}

// ---------------- input GEMM: XG[t][dir][b][g] = A @ Wih^T + (bih+bhh) ----------------
#define BM 128
#define BN 128
#define BK 16
#define SAST 20

__global__ void __launch_bounds__(256) igemm_kernel(
    const float* __restrict__ Ax, int useH0,
    const float* __restrict__ Wf, const float* __restrict__ Wb,
    const float* __restrict__ bif, const float* __restrict__ bhf,
    const float* __restrict__ bib, const float* __restrict__ bhb) {
    __shared__ float sA[2][BM][SAST];
    __shared__ float sB[2][BN][SAST];

    const float* A = useH0 ? (const float*)d_H0 : Ax;
    const int dir = blockIdx.z;
    const float* W = dir ? Wb : Wf;
    const float* bi = dir ? bib : bif;
    const float* bh = dir ? bhb : bhf;
    const int m0 = blockIdx.y * BM;
    const int n0 = blockIdx.x * BN;
    const int tid = threadIdx.x;
    const int w = tid >> 5, lane = tid & 31;
    const int wm = w >> 2, wn = w & 3;
    const int g_ = lane >> 2, tg = lane & 3;

    float acc[4][4][4];
#pragma unroll
    for (int i = 0; i < 4; i++)
#pragma unroll
        for (int j = 0; j < 4; j++)
#pragma unroll
            for (int q = 0; q < 4; q++) acc[i][j][q] = 0.f;

    auto load_stage = [&](int s, int k0) {
#pragma unroll
        for (int i = 0; i < 2; i++) {
            int c = tid + i * 256;
            int row = c >> 2, cc = c & 3;
            cp16(&sA[s][row][cc * 4], A + (size_t)(m0 + row) * CIN + k0 + cc * 4);
            cp16(&sB[s][row][cc * 4], W + (size_t)(n0 + row) * CIN + k0 + cc * 4);
        }
        asm volatile("cp.async.commit_group;");
    };

    load_stage(0, 0);
    const int KT = CIN / BK;
    for (int kt = 0; kt < KT; kt++) {
        if (kt < KT - 1) {
            load_stage((kt + 1) & 1, (kt + 1) * BK);
            asm volatile("cp.async.wait_group 1;");
        } else {
            asm volatile("cp.async.wait_group 0;");
        }
        __syncthreads();
        const int s = kt & 1;
#pragma unroll
        for (int kk = 0; kk < BK; kk += 8) {
            unsigned a[4][4], b[4][2];
#pragma unroll
            for (int mt = 0; mt < 4; mt++) {
                int r = wm * 64 + mt * 16 + g_;
                a[mt][0] = f2tf(sA[s][r][kk + tg]);
                a[mt][1] = f2tf(sA[s][r + 8][kk + tg]);
                a[mt][2] = f2tf(sA[s][r][kk + tg + 4]);
                a[mt][3] = f2tf(sA[s][r + 8][kk + tg + 4]);
            }
#pragma unroll
            for (int nt = 0; nt < 4; nt++) {
                int n = wn * 32 + nt * 8 + g_;
                b[nt][0] = f2tf(sB[s][n][kk + tg]);
                b[nt][1] = f2tf(sB[s][n][kk + tg + 4]);
            }
#pragma unroll
            for (int mt = 0; mt < 4; mt++)
#pragma unroll
                for (int nt = 0; nt < 4; nt++) mma_tf32(acc[mt][nt], a[mt], b[nt]);
        }
        __syncthreads();
    }

#pragma unroll
    for (int mt = 0; mt < 4; mt++) {
#pragma unroll
        for (int nt = 0; nt < 4; nt++) {
            int col = n0 + wn * 32 + nt * 8 + tg * 2;
            float b0v = bi[col] + bh[col];
            float b1v = bi[col + 1] + bh[col + 1];
#pragma unroll
            for (int hh = 0; hh < 2; hh++) {
                int row = m0 + wm * 64 + mt * 16 + g_ + hh * 8;
                int tt = row >> 8, bb = row & 255;
                float2 v;
                v.x = acc[mt][nt][hh * 2 + 0] + b0v;
                v.y = acc[mt][nt][hh * 2 + 1] + b1v;
                *(float2*)&d_XG[(((size_t)tt * 2 + dir) * BB + bb) * GG + col] = v;
            }
        }
    }
}

// ---------------- persistent recurrence kernel ----------------
// 128 CTAs. CTA -> (dir, btile, jg): owns b rows [b0,b0+64), gate cols {q*256 + j0..j0+16}.
// Group = (dir,btile): 16 CTAs, one group barrier per step, fused pointwise, c in regs.
#define SMEMREC (2 * 64 * WPITCH * 4)

__global__ void __launch_bounds__(256) recur_kernel(
    const float* __restrict__ Whf, const float* __restrict__ Whb,
    float* __restrict__ outp, int writeOut) {
    extern __shared__ float sm[];
    float* ws = sm;                 // [64][WPITCH] gate-interleaved, tf32-rounded, pair-swizzled Whh
    float* hs = sm + 64 * WPITCH;   // [64][WPITCH] h tile (pair-swizzled); reused as gate-exchange sg

    const int cta = blockIdx.x;
    const int tid = threadIdx.x;
    const int dir = cta >> 6;
    const int sub = cta & 63;
    const int btile = sub >> 4;
    const int jg = sub & 15;
    const int b0 = btile * 64;
    const int j0 = jg * 16;
    const float* Wh = dir ? Whb : Whf;
    float* outb = writeOut ? outp : (float*)d_H0;
    unsigned* flag = &d_gflags[(dir * 4 + btile) * 32];

    const int w = tid >> 5, lane = tid & 31;
    const int wm = w >> 2, wn = w & 3; // 2(M) x 4(N) warps; warp tile 32 x 16; wn == gate q
    const int g_ = lane >> 2, tg = lane & 3;

    // --- build weight slice: row r = q*16+jj  <->  Whh row q*256 + j0 + jj ; cols pair-swizzled
    for (int i = tid; i < 64 * 256; i += 256) {
        int r = i >> 8, k = i & 255;
        int q = r >> 4, jj = r & 15;
        float v = tf32r(Wh[(size_t)(q * 256 + j0 + jj) * HH + k]);
        ws[r * WPITCH + pswz(k)] = v;
    }

    // --- pointwise ownership: thread t -> b row b0+(t>>2), h cols j0+(t&3)*4 .. +3
    const int prb = tid >> 2;
    const int pj = j0 + (tid & 3) * 4;
    float4 cst = make_float4(0.f, 0.f, 0.f, 0.f);
    // zero-init swizzled h state (zeros are position-independent)
    *(float4*)&d_HstS[(dir * BB + b0 + prb) * HH + pj] = cst;

    // --- XG prefetch registers
    float2 xgr[2][2][2];
    auto prefetchXG = [&](int s) {
        int t = dir ? (TT - 1 - s) : s;
        const float* base = d_XG + ((size_t)t * 2 + dir) * BB * GG;
#pragma unroll
        for (int mt = 0; mt < 2; mt++)
#pragma unroll
            for (int nt = 0; nt < 2; nt++)
#pragma unroll
                for (int hh = 0; hh < 2; hh++) {
                    int row = b0 + wm * 32 + mt * 16 + g_ + hh * 8;
                    int gcol = wn * 256 + j0 + nt * 8 + tg * 2;
                    xgr[mt][nt][hh] = __ldcg((const float2*)&base[(size_t)row * GG + gcol]);
                }
    };

    prefetchXG(0);
    unsigned cnt = 16;
    gbar(flag, cnt); // h0 visible group-wide

    const float* hA = hs + (wm * 32 + g_) * WPITCH + tg * 2;
    const float* wB = ws + (wn * 16 + g_) * WPITCH + tg * 2;

    for (int s = 0; s < TT; s++) {
        const int t = dir ? (TT - 1 - s) : s;

        // --- h tile fill via cp.async (data already tf32-rounded + pair-swizzled), 2 halves
#pragma unroll
        for (int half = 0; half < 2; half++) {
            for (int i = tid; i < 64 * 32; i += 256) { // 16B chunks
                int r = i >> 5, c4 = (i & 31) + half * 32;
                cp16(&hs[r * WPITCH + c4 * 4],
                     &d_HstS[(size_t)(dir * BB + b0 + r) * HH + c4 * 4]);
            }
            asm volatile("cp.async.commit_group;");
        }

        float acc[2][2][4];
#pragma unroll
        for (int i = 0; i < 2; i++)
#pragma unroll
            for (int j = 0; j < 2; j++)
#pragma unroll
                for (int q = 0; q < 4; q++) acc[i][j][q] = 0.f;

        asm volatile("cp.async.wait_group 1;");
        __syncthreads();

#pragma unroll
        for (int phase = 0; phase < 2; phase++) {
#pragma unroll 8
            for (int k8 = phase * 16; k8 < phase * 16 + 16; k8++) {
                const int kk = k8 * 8;
                uint2 aL[2], aH[2], bb[2];
#pragma unroll
                for (int mt = 0; mt < 2; mt++) {
                    aL[mt] = *(const uint2*)(hA + mt * 16 * WPITCH + kk);
                    aH[mt] = *(const uint2*)(hA + (mt * 16 + 8) * WPITCH + kk);
                }
#pragma unroll
                for (int nt = 0; nt < 2; nt++)
                    bb[nt] = *(const uint2*)(wB + nt * 8 * WPITCH + kk);
#pragma unroll
                for (int mt = 0; mt < 2; mt++) {
                    unsigned a[4] = {aL[mt].x, aH[mt].x, aL[mt].y, aH[mt].y};
#pragma unroll
                    for (int nt = 0; nt < 2; nt++) {
                        unsigned b[2] = {bb[nt].x, bb[nt].y};
                        mma_tf32(acc[mt][nt], a, b);
                    }
                }
            }
            if (phase == 0) {
                asm volatile("cp.async.wait_group 0;");
                __syncthreads();
            }
        }

        // --- gate exchange through smem (overwrites hs region)
        __syncthreads();
        float* sg = hs;
#pragma unroll
        for (int mt = 0; mt < 2; mt++)
#pragma unroll
            for (int nt = 0; nt < 2; nt++)
#pragma unroll
                for (int hh = 0; hh < 2; hh++) {
                    int row = wm * 32 + mt * 16 + g_ + hh * 8;
                    int col = wn * 16 + nt * 8 + tg * 2;
                    float2 v;
                    v.x = acc[mt][nt][hh * 2 + 0] + xgr[mt][nt][hh].x;
                    v.y = acc[mt][nt][hh * 2 + 1] + xgr[mt][nt][hh].y;
                    *(float2*)&sg[row * SGPITCH + col] = v;
                }
        __syncthreads();

        // --- fused LSTM cell, c-state in registers
        {
            int jj4 = (tid & 3) * 4;
            const float* rowp = &sg[prb * SGPITCH];
            float4 gi = *(const float4*)(rowp + jj4);
            float4 gf = *(const float4*)(rowp + 16 + jj4);
            float4 gc = *(const float4*)(rowp + 32 + jj4);
            float4 go = *(const float4*)(rowp + 48 + jj4);
            cst.x = sigf(gf.x) * cst.x + sigf(gi.x) * tanhf(gc.x);
            cst.y = sigf(gf.y) * cst.y + sigf(gi.y) * tanhf(gc.y);
            cst.z = sigf(gf.z) * cst.z + sigf(gi.z) * tanhf(gc.z);
            cst.w = sigf(gf.w) * cst.w + sigf(gi.w) * tanhf(gc.w);
            float4 hv;
            hv.x = sigf(go.x) * tanhf(cst.x);
            hv.y = sigf(go.y) * tanhf(cst.y);
            hv.z = sigf(go.z) * tanhf(cst.z);
            hv.w = sigf(go.w) * tanhf(cst.w);
            // full-precision output
            *(float4*)&outb[((size_t)t * BB + b0 + prb) * (2 * HH) + dir * HH + pj] = hv;
            // rounded + pair-swizzled state for next step's GEMM
            float* hp = &d_HstS[(size_t)(dir * BB + b0 + prb) * HH + (pj & ~7) + ((pj >> 2) & 1)];
            hp[0] = tf32r(hv.x);
            hp[2] = tf32r(hv.y);
            hp[4] = tf32r(hv.z);
            hp[6] = tf32r(hv.w);
        }

        if (s + 1 < TT) prefetchXG(s + 1); // in flight across the barrier wait
        cnt += 16;
        gbar(flag, cnt);
    }

    // --- reset group flag for next launch / graph replay (leader waits for everyone)
    __syncthreads();
    if (tid == 0) {
        atomicAdd(flag, 1u);
        if (jg == 0) {
            unsigned tgt = 16u * (TT + 2);
            while (*(volatile unsigned*)flag < tgt) {}
            *(volatile unsigned*)flag = 0u;
        }
    }
}

// ---------------- launch ----------------
extern "C" void kernel_launch(void* const* d_in, const int* in_sizes, int n_in,
                              void* d_out, int out_size) {
    (void)in_sizes; (void)n_in; (void)out_size;
    const float* x = (const float*)d_in[0];
    const float* wih0f = (const float*)d_in[1];
    const float* whh0f = (const float*)d_in[2];
    const float* bih0f = (const float*)d_in[3];
    const float* bhh0f = (const float*)d_in[4];
    const float* wih0b = (const float*)d_in[5];
    const float* whh0b = (const float*)d_in[6];
    const float* bih0b = (const float*)d_in[7];
    const float* bhh0b = (const float*)d_in[8];
    const float* wih1f = (const float*)d_in[9];
    const float* whh1f = (const float*)d_in[10];
    const float* bih1f = (const float*)d_in[11];
    const float* bhh1f = (const float*)d_in[12];
    const float* wih1b = (const float*)d_in[13];
    const float* whh1b = (const float*)d_in[14];
    const float* bih1b = (const float*)d_in[15];
    const float* bhh1b = (const float*)d_in[16];
    float* out = (float*)d_out;

    cudaFuncSetAttribute(recur_kernel, cudaFuncAttributeMaxDynamicSharedMemorySize, SMEMREC);

    dim3 gg(GG / BN, (TT * BB) / BM, 2);

    igemm_kernel<<<gg, 256>>>(x, 0, wih0f, wih0b, bih0f, bhh0f, bih0b, bhh0b);
    recur_kernel<<<RNCTA, 256, SMEMREC>>>(whh0f, whh0b, nullptr, 0);
    igemm_kernel<<<gg, 256>>>(nullptr, 1, wih1f, wih1b, bih1f, bhh1f, bih1b, bhh1b);
    recur_kernel<<<RNCTA, 256, SMEMREC>>>(whh1f, whh1b, out, 1);
}